// round 7
// baseline (speedup 1.0000x reference)
#include <cuda_runtime.h>

// db2 inverse DWT (synthesis), polyphase form, 4 input cols x 1 row per thread.
// x: [32, 512, 512, 4] NHWC f32  ->  y: [32, 1024, 1024, 1] f32

#define IN_H 512
#define IN_W 512
#define IN_B 32

struct F8 { float4 a, b; };

// 256-bit load (default cache policy). p must be 32B-aligned.
__device__ __forceinline__ F8 ldg8(const float4* p) {
    unsigned r0,r1,r2,r3,r4,r5,r6,r7;
    asm volatile("ld.global.nc.v8.b32 {%0,%1,%2,%3,%4,%5,%6,%7}, [%8];"
                 : "=r"(r0), "=r"(r1), "=r"(r2), "=r"(r3),
                   "=r"(r4), "=r"(r5), "=r"(r6), "=r"(r7)
                 : "l"(p));
    F8 v;
    v.a = make_float4(__uint_as_float(r0), __uint_as_float(r1),
                      __uint_as_float(r2), __uint_as_float(r3));
    v.b = make_float4(__uint_as_float(r4), __uint_as_float(r5),
                      __uint_as_float(r6), __uint_as_float(r7));
    return v;
}

__device__ __forceinline__ void stcs4(float4* p, float4 v) {
    asm volatile("st.global.cs.v4.f32 [%0], {%1,%2,%3,%4};"
                 :: "l"(p), "f"(v.x), "f"(v.y), "f"(v.z), "f"(v.w) : "memory");
}

// One input quad -> 2x2 output block.
__device__ __forceinline__ void quad2x2(
    const float4& v00, const float4& v01,
    const float4& v10, const float4& v11,
    const float L[2][2], const float G[2][2],
    float out[2][2])
{
    float a0[2] = { v00.x + v00.y, v10.x + v10.y };
    float a1[2] = { v01.x + v01.y, v11.x + v11.y };
    float z0[2] = { v00.z, v10.z };
    float z1[2] = { v01.z, v11.z };
    float w0[2] = { v00.w, v10.w };
    float w1[2] = { v01.w, v11.w };

    float r_az[2][2], r_w[2][2];
#pragma unroll
    for (int dv = 0; dv < 2; ++dv) {
#pragma unroll
        for (int ah = 0; ah < 2; ++ah) {
            float r = L[ah][0] * a0[dv];
            r = fmaf(L[ah][1], a1[dv], r);
            r = fmaf(G[ah][0], z0[dv], r);
            r = fmaf(G[ah][1], z1[dv], r);
            r_az[dv][ah] = r;
            r_w[dv][ah] = fmaf(G[ah][0], w0[dv], G[ah][1] * w1[dv]);
        }
    }
#pragma unroll
    for (int av = 0; av < 2; ++av) {
#pragma unroll
        for (int ah = 0; ah < 2; ++ah) {
            float r = L[av][0] * r_az[0][ah];
            r = fmaf(L[av][1], r_az[1][ah], r);
            r = fmaf(G[av][0], r_w[0][ah], r);
            r = fmaf(G[av][1], r_w[1][ah], r);
            out[av][ah] = r;
        }
    }
}

__global__ __launch_bounds__(256)
void idwt_db2_kernel(const float4* __restrict__ x, float4* __restrict__ y) {
    const int uu = blockIdx.x * blockDim.x + threadIdx.x;
    const int q  = uu & 127;        // 0..127 (group of 4 input cols)
    const int s  = uu >> 7;         // 0..511 (input row)
    const int b  = blockIdx.z;      // 0..31

    const float h0 = 0.48296291314469025f;
    const float h1 = 0.83651630373780790f;
    const float h2 = 0.22414386804185735f;
    const float h3 = -0.12940952255092145f;
    const float L[2][2] = { { h2,  h0 }, {  h3,  h1 } };
    const float G[2][2] = { { h1,  h3 }, { -h0, -h2 } };

    const int t0 = 4 * q;                       // owned cols t0..t0+3
    const int t4 = min(4 * q + 4, IN_W - 1);    // halo col
    const int s1 = min(s + 1, IN_H - 1);

    const size_t r0 = ((size_t)b * IN_H + s ) * IN_W;
    const size_t r1 = ((size_t)b * IN_H + s1) * IN_W;

    // 6 loads issued up front: 4x 32B owned + 2x 16B halo (MLP=6, 160B/thread)
    const F8     A01 = ldg8(&x[r0 + t0]);
    const F8     A23 = ldg8(&x[r0 + t0 + 2]);
    const F8     B01 = ldg8(&x[r1 + t0]);
    const F8     B23 = ldg8(&x[r1 + t0 + 2]);
    const float4 A4  = __ldg(&x[r0 + t4]);
    const float4 B4  = __ldg(&x[r1 + t4]);

    float o0[2][2], o1[2][2], o2[2][2], o3[2][2];
    quad2x2(A01.a, A01.b, B01.a, B01.b, L, G, o0);  // out cols 8q+0..1
    quad2x2(A01.b, A23.a, B01.b, B23.a, L, G, o1);  // out cols 8q+2..3
    quad2x2(A23.a, A23.b, B23.a, B23.b, L, G, o2);  // out cols 8q+4..5
    quad2x2(A23.b, A4,    B23.b, B4,    L, G, o3);  // out cols 8q+6..7

    // output rows 2s, 2s+1; 2x float4 per row (32B contiguous per thread)
    const size_t ob = ((size_t)b * 1024 + 2 * s) * 256 + 2 * q;
    stcs4(&y[ob],           make_float4(o0[0][0], o0[0][1], o1[0][0], o1[0][1]));
    stcs4(&y[ob + 1],       make_float4(o2[0][0], o2[0][1], o3[0][0], o3[0][1]));
    stcs4(&y[ob + 256],     make_float4(o0[1][0], o0[1][1], o1[1][0], o1[1][1]));
    stcs4(&y[ob + 256 + 1], make_float4(o2[1][0], o2[1][1], o3[1][0], o3[1][1]));
}

extern "C" void kernel_launch(void* const* d_in, const int* in_sizes, int n_in,
                              void* d_out, int out_size) {
    const float4* x = (const float4*)d_in[0];
    float4* y = (float4*)d_out;
    dim3 block(256, 1, 1);
    // 128 col-groups * 512 rows = 65536 threads per image / 256 = 256 blocks
    dim3 grid((128 * 512) / 256, 1, IN_B);
    idwt_db2_kernel<<<grid, block>>>(x, y);
}

// round 8
// speedup vs baseline: 1.2816x; 1.2816x over previous
#include <cuda_runtime.h>

// db2 inverse DWT (synthesis), polyphase. 2 input cols x 1 row per thread,
// block = one full input row (256 threads). Horizontal halo via warp shuffle
// (only lane 31 loads it); vertical halo via L2. Streaming (.cs) stores.
// x: [32, 512, 512, 4] NHWC f32  ->  y: [32, 1024, 1024, 1] f32

#define IN_H 512
#define IN_W 512
#define IN_B 32

struct F8 { float4 a, b; };

// 256-bit load (default policy). p must be 32B-aligned.
__device__ __forceinline__ F8 ldg8(const float4* p) {
    unsigned r0,r1,r2,r3,r4,r5,r6,r7;
    asm volatile("ld.global.nc.v8.b32 {%0,%1,%2,%3,%4,%5,%6,%7}, [%8];"
                 : "=r"(r0), "=r"(r1), "=r"(r2), "=r"(r3),
                   "=r"(r4), "=r"(r5), "=r"(r6), "=r"(r7)
                 : "l"(p));
    F8 v;
    v.a = make_float4(__uint_as_float(r0), __uint_as_float(r1),
                      __uint_as_float(r2), __uint_as_float(r3));
    v.b = make_float4(__uint_as_float(r4), __uint_as_float(r5),
                      __uint_as_float(r6), __uint_as_float(r7));
    return v;
}

__device__ __forceinline__ void stcs4(float4* p, float4 v) {
    asm volatile("st.global.cs.v4.f32 [%0], {%1,%2,%3,%4};"
                 :: "l"(p), "f"(v.x), "f"(v.y), "f"(v.z), "f"(v.w) : "memory");
}

__device__ __forceinline__ float4 shfl_down_f4(float4 v) {
    float4 r;
    r.x = __shfl_down_sync(0xffffffffu, v.x, 1);
    r.y = __shfl_down_sync(0xffffffffu, v.y, 1);
    r.z = __shfl_down_sync(0xffffffffu, v.z, 1);
    r.w = __shfl_down_sync(0xffffffffu, v.w, 1);
    return r;
}

__device__ __forceinline__ void quad2x2(
    const float4& v00, const float4& v01,
    const float4& v10, const float4& v11,
    const float L[2][2], const float G[2][2],
    float out[2][2])
{
    float a0[2] = { v00.x + v00.y, v10.x + v10.y };
    float a1[2] = { v01.x + v01.y, v11.x + v11.y };
    float z0[2] = { v00.z, v10.z };
    float z1[2] = { v01.z, v11.z };
    float w0[2] = { v00.w, v10.w };
    float w1[2] = { v01.w, v11.w };

    float r_az[2][2], r_w[2][2];
#pragma unroll
    for (int dv = 0; dv < 2; ++dv) {
#pragma unroll
        for (int ah = 0; ah < 2; ++ah) {
            float r = L[ah][0] * a0[dv];
            r = fmaf(L[ah][1], a1[dv], r);
            r = fmaf(G[ah][0], z0[dv], r);
            r = fmaf(G[ah][1], z1[dv], r);
            r_az[dv][ah] = r;
            r_w[dv][ah] = fmaf(G[ah][0], w0[dv], G[ah][1] * w1[dv]);
        }
    }
#pragma unroll
    for (int av = 0; av < 2; ++av) {
#pragma unroll
        for (int ah = 0; ah < 2; ++ah) {
            float r = L[av][0] * r_az[0][ah];
            r = fmaf(L[av][1], r_az[1][ah], r);
            r = fmaf(G[av][0], r_w[0][ah], r);
            r = fmaf(G[av][1], r_w[1][ah], r);
            out[av][ah] = r;
        }
    }
}

__global__ __launch_bounds__(256)
void idwt_db2_kernel(const float4* __restrict__ x, float4* __restrict__ y) {
    const int u    = threadIdx.x;          // 0..255 (col pair); block = one row
    const int s    = blockIdx.x;           // 0..511
    const int b    = blockIdx.z;           // 0..31
    const int lane = u & 31;

    const float h0 = 0.48296291314469025f;
    const float h1 = 0.83651630373780790f;
    const float h2 = 0.22414386804185735f;
    const float h3 = -0.12940952255092145f;
    const float L[2][2] = { { h2,  h0 }, {  h3,  h1 } };
    const float G[2][2] = { { h1,  h3 }, { -h0, -h2 } };

    const int t0 = 2 * u;
    const int t2 = min(t0 + 2, IN_W - 1);
    const int s1 = min(s + 1, IN_H - 1);

    const size_t r0 = ((size_t)b * IN_H + s ) * IN_W;
    const size_t r1 = ((size_t)b * IN_H + s1) * IN_W;

    // Lane 31's halo loads, predicated, issued first.
    float4 Ah31, Bh31;
    if (lane == 31) {
        Ah31 = __ldg(&x[r0 + t2]);
        Bh31 = __ldg(&x[r1 + t2]);
    }
    // Owned 32B loads (cols t0, t0+1), two rows.
    const F8 A = ldg8(&x[r0 + t0]);
    const F8 B = ldg8(&x[r1 + t0]);

    // Horizontal halo (col t0+2) = next lane's first float4.
    float4 Ah = shfl_down_f4(A.a);
    float4 Bh = shfl_down_f4(B.a);
    if (lane == 31) { Ah = Ah31; Bh = Bh31; }

    float oA[2][2], oB[2][2];
    quad2x2(A.a, A.b, B.a, B.b, L, G, oA);   // out cols 4u..4u+1
    quad2x2(A.b, Ah,  B.b, Bh,  L, G, oB);   // out cols 4u+2..4u+3

    const size_t ob = ((size_t)b * 1024 + 2 * s) * 256 + u;
    stcs4(&y[ob],       make_float4(oA[0][0], oA[0][1], oB[0][0], oB[0][1]));
    stcs4(&y[ob + 256], make_float4(oA[1][0], oA[1][1], oB[1][0], oB[1][1]));
}

extern "C" void kernel_launch(void* const* d_in, const int* in_sizes, int n_in,
                              void* d_out, int out_size) {
    const float4* x = (const float4*)d_in[0];
    float4* y = (float4*)d_out;
    dim3 block(256, 1, 1);
    dim3 grid(IN_H, 1, IN_B);
    idwt_db2_kernel<<<grid, block>>>(x, y);
}

// round 9
// speedup vs baseline: 1.2911x; 1.0074x over previous
#include <cuda_runtime.h>
#include <cstdint>

// db2 inverse DWT (synthesis), polyphase. 2 input cols x 1 row per thread,
// block = one input row. Horizontal halo via warp shuffle. Output staged in
// smem (2 full output rows = 8KB contiguous) and written with a single
// cp.async.bulk store per block for burst-coherent DRAM writes.
// x: [32, 512, 512, 4] NHWC f32  ->  y: [32, 1024, 1024, 1] f32

#define IN_H 512
#define IN_W 512
#define IN_B 32

struct F8 { float4 a, b; };

__device__ __forceinline__ F8 ldg8(const float4* p) {
    unsigned r0,r1,r2,r3,r4,r5,r6,r7;
    asm volatile("ld.global.nc.v8.b32 {%0,%1,%2,%3,%4,%5,%6,%7}, [%8];"
                 : "=r"(r0), "=r"(r1), "=r"(r2), "=r"(r3),
                   "=r"(r4), "=r"(r5), "=r"(r6), "=r"(r7)
                 : "l"(p));
    F8 v;
    v.a = make_float4(__uint_as_float(r0), __uint_as_float(r1),
                      __uint_as_float(r2), __uint_as_float(r3));
    v.b = make_float4(__uint_as_float(r4), __uint_as_float(r5),
                      __uint_as_float(r6), __uint_as_float(r7));
    return v;
}

__device__ __forceinline__ float4 shfl_down_f4(float4 v) {
    float4 r;
    r.x = __shfl_down_sync(0xffffffffu, v.x, 1);
    r.y = __shfl_down_sync(0xffffffffu, v.y, 1);
    r.z = __shfl_down_sync(0xffffffffu, v.z, 1);
    r.w = __shfl_down_sync(0xffffffffu, v.w, 1);
    return r;
}

__device__ __forceinline__ void quad2x2(
    const float4& v00, const float4& v01,
    const float4& v10, const float4& v11,
    const float L[2][2], const float G[2][2],
    float out[2][2])
{
    float a0[2] = { v00.x + v00.y, v10.x + v10.y };
    float a1[2] = { v01.x + v01.y, v11.x + v11.y };
    float z0[2] = { v00.z, v10.z };
    float z1[2] = { v01.z, v11.z };
    float w0[2] = { v00.w, v10.w };
    float w1[2] = { v01.w, v11.w };

    float r_az[2][2], r_w[2][2];
#pragma unroll
    for (int dv = 0; dv < 2; ++dv) {
#pragma unroll
        for (int ah = 0; ah < 2; ++ah) {
            float r = L[ah][0] * a0[dv];
            r = fmaf(L[ah][1], a1[dv], r);
            r = fmaf(G[ah][0], z0[dv], r);
            r = fmaf(G[ah][1], z1[dv], r);
            r_az[dv][ah] = r;
            r_w[dv][ah] = fmaf(G[ah][0], w0[dv], G[ah][1] * w1[dv]);
        }
    }
#pragma unroll
    for (int av = 0; av < 2; ++av) {
#pragma unroll
        for (int ah = 0; ah < 2; ++ah) {
            float r = L[av][0] * r_az[0][ah];
            r = fmaf(L[av][1], r_az[1][ah], r);
            r = fmaf(G[av][0], r_w[0][ah], r);
            r = fmaf(G[av][1], r_w[1][ah], r);
            out[av][ah] = r;
        }
    }
}

__global__ __launch_bounds__(256)
void idwt_db2_kernel(const float4* __restrict__ x, float4* __restrict__ y) {
    __shared__ float4 buf[512];            // 2 output rows, 8KB, gmem-contiguous

    const int u    = threadIdx.x;          // 0..255 (col pair); block = one row
    const int s    = blockIdx.x;           // 0..511
    const int b    = blockIdx.z;           // 0..31
    const int lane = u & 31;

    const float h0 = 0.48296291314469025f;
    const float h1 = 0.83651630373780790f;
    const float h2 = 0.22414386804185735f;
    const float h3 = -0.12940952255092145f;
    const float L[2][2] = { { h2,  h0 }, {  h3,  h1 } };
    const float G[2][2] = { { h1,  h3 }, { -h0, -h2 } };

    const int t0 = 2 * u;
    const int t2 = min(t0 + 2, IN_W - 1);
    const int s1 = min(s + 1, IN_H - 1);

    const size_t r0 = ((size_t)b * IN_H + s ) * IN_W;
    const size_t r1 = ((size_t)b * IN_H + s1) * IN_W;

    float4 Ah31, Bh31;
    if (lane == 31) {
        Ah31 = __ldg(&x[r0 + t2]);
        Bh31 = __ldg(&x[r1 + t2]);
    }
    const F8 A = ldg8(&x[r0 + t0]);
    const F8 B = ldg8(&x[r1 + t0]);

    float4 Ah = shfl_down_f4(A.a);
    float4 Bh = shfl_down_f4(B.a);
    if (lane == 31) { Ah = Ah31; Bh = Bh31; }

    float oA[2][2], oB[2][2];
    quad2x2(A.a, A.b, B.a, B.b, L, G, oA);   // out cols 4u..4u+1
    quad2x2(A.b, Ah,  B.b, Bh,  L, G, oB);   // out cols 4u+2..4u+3

    buf[u]       = make_float4(oA[0][0], oA[0][1], oB[0][0], oB[0][1]);
    buf[u + 256] = make_float4(oA[1][0], oA[1][1], oB[1][0], oB[1][1]);
    __syncthreads();

    if (u == 0) {
        uint32_t saddr;
        asm("{ .reg .u64 t; cvta.to.shared.u64 t, %1; cvt.u32.u64 %0, t; }"
            : "=r"(saddr) : "l"(buf));
        const float4* gdst = &y[((size_t)b * 1024 + 2 * s) * 256];
        asm volatile("fence.proxy.async.shared::cta;" ::: "memory");
        asm volatile("cp.async.bulk.global.shared::cta.bulk_group [%0], [%1], %2;"
                     :: "l"(gdst), "r"(saddr), "r"(8192) : "memory");
        asm volatile("cp.async.bulk.commit_group;" ::: "memory");
        asm volatile("cp.async.bulk.wait_group.read 0;" ::: "memory");
    }
}

extern "C" void kernel_launch(void* const* d_in, const int* in_sizes, int n_in,
                              void* d_out, int out_size) {
    const float4* x = (const float4*)d_in[0];
    float4* y = (float4*)d_out;
    dim3 block(256, 1, 1);
    dim3 grid(IN_H, 1, IN_B);
    idwt_db2_kernel<<<grid, block>>>(x, y);
}